// round 1
// baseline (speedup 1.0000x reference)
#include <cuda_runtime.h>
#include <cuda_bf16.h>
#include <math.h>

// ---------------------------------------------------------------------------
// MiniGPT forward, fp32 baseline.
// B=4, T=1024, C=1024, H=16, HD=64, L=8, V=32000.
// ---------------------------------------------------------------------------

#define BATCH 4
#define TLEN 1024
#define CDIM 1024
#define NHEAD 16
#define HDIM 64
#define NLAYER 8
#define VOCAB 32000
#define NTOK (BATCH * TLEN)          // 4096
#define FF (4 * CDIM)                // 4096

// ---------------- device scratch (static, no allocation) -------------------
__device__ float g_x[NTOK * CDIM];                 // residual stream   16 MB
__device__ float g_h[NTOK * CDIM];                 // LN output         16 MB
__device__ float g_qkv[NTOK * 3 * CDIM];           // fused QKV         48 MB
__device__ float g_o[NTOK * CDIM];                 // attn out          16 MB
__device__ float g_ff[NTOK * FF];                  // MLP hidden        64 MB
__device__ float g_scores[(size_t)BATCH * NHEAD * TLEN * TLEN]; // 256 MB
__device__ float g_wqkv[(size_t)NLAYER * CDIM * 3 * CDIM];      //  96 MB

// ---------------------------------------------------------------------------
// Pack wq/wk/wv [L,H,C,HD] -> fused [L, C, 3C] with col j = h*64+d (+1024 K, +2048 V)
// ---------------------------------------------------------------------------
__global__ void pack_qkv_kernel(const float* __restrict__ wq,
                                const float* __restrict__ wk,
                                const float* __restrict__ wv,
                                float* __restrict__ wqkv) {
    size_t i = (size_t)blockIdx.x * blockDim.x + threadIdx.x;
    const size_t total = (size_t)NLAYER * NHEAD * CDIM * HDIM; // 8,388,608
    if (i >= total) return;
    int d = (int)(i & 63);
    int c = (int)((i >> 6) & 1023);
    int h = (int)((i >> 16) & 15);
    int l = (int)(i >> 20);
    size_t dst = ((size_t)l * CDIM + c) * (3 * CDIM) + h * HDIM + d;
    wqkv[dst]            = wq[i];
    wqkv[dst + CDIM]     = wk[i];
    wqkv[dst + 2 * CDIM] = wv[i];
}

// ---------------------------------------------------------------------------
// Embedding: x[b,t,:] = tok_emb[idx[b,t],:] + pos_emb[t,:]
// ---------------------------------------------------------------------------
__global__ void embed_kernel(const int* __restrict__ idx,
                             const float* __restrict__ tok,
                             const float* __restrict__ pos,
                             float* __restrict__ x) {
    int row = blockIdx.x;                 // 0..4095
    int t = row & (TLEN - 1);
    int token = idx[row];
    const float4* te = (const float4*)(tok + (size_t)token * CDIM);
    const float4* pe = (const float4*)(pos + (size_t)t * CDIM);
    float4* xo = (float4*)(x + (size_t)row * CDIM);
    int i = threadIdx.x;                  // 256 threads x float4 = 1024
    float4 a = te[i], b = pe[i];
    a.x += b.x; a.y += b.y; a.z += b.z; a.w += b.w;
    xo[i] = a;
}

// ---------------------------------------------------------------------------
// LayerNorm over rows of length 1024. 256 threads per row.
// ---------------------------------------------------------------------------
__global__ void ln_kernel(const float* __restrict__ x,
                          const float* __restrict__ g,
                          const float* __restrict__ b,
                          float* __restrict__ out) {
    int row = blockIdx.x;
    int tid = threadIdx.x;
    const float4* xr = (const float4*)(x + (size_t)row * CDIM);
    float4 v = xr[tid];
    float s  = v.x + v.y + v.z + v.w;
    float ss = v.x * v.x + v.y * v.y + v.z * v.z + v.w * v.w;
    #pragma unroll
    for (int o = 16; o > 0; o >>= 1) {
        s  += __shfl_xor_sync(0xffffffffu, s,  o);
        ss += __shfl_xor_sync(0xffffffffu, ss, o);
    }
    __shared__ float sm[8], sm2[8];
    int w = tid >> 5, lane = tid & 31;
    if (lane == 0) { sm[w] = s; sm2[w] = ss; }
    __syncthreads();
    s = 0.f; ss = 0.f;
    #pragma unroll
    for (int i = 0; i < 8; i++) { s += sm[i]; ss += sm2[i]; }
    float mean = s * (1.0f / CDIM);
    float var  = ss * (1.0f / CDIM) - mean * mean;
    float rstd = rsqrtf(var + 1e-5f);
    float4 gv = ((const float4*)g)[tid];
    float4 bv = ((const float4*)b)[tid];
    float4 o;
    o.x = (v.x - mean) * rstd * gv.x + bv.x;
    o.y = (v.y - mean) * rstd * gv.y + bv.y;
    o.z = (v.z - mean) * rstd * gv.z + bv.z;
    o.w = (v.w - mean) * rstd * gv.w + bv.w;
    ((float4*)(out + (size_t)row * CDIM))[tid] = o;
}

// ---------------------------------------------------------------------------
// SGEMM: C[M,N] = A[M,K] * B[K,N]  (+bias[n]) (+res) (relu)
// BM=BN=128, BK=8, TM=TN=8, 256 threads. All dims multiples of tile sizes.
// ---------------------------------------------------------------------------
__global__ __launch_bounds__(256)
void sgemm_kernel(const float* __restrict__ A, const float* __restrict__ B,
                  float* __restrict__ C, int M, int N, int K,
                  const float* __restrict__ bias,
                  const float* __restrict__ res, int relu) {
    __shared__ float As[8][128];
    __shared__ float Bs[8][128];
    int bx = blockIdx.x;     // N tile
    int by = blockIdx.y;     // M tile
    int tid = threadIdx.x;
    int tr = tid >> 4;       // 0..15  (row group of 8)
    int tc = tid & 15;       // 0..15  (col group of 8)

    int arow = tid >> 1;            // 0..127
    int acol = (tid & 1) * 4;       // 0 or 4
    int brow = tid >> 5;            // 0..7
    int bcol = (tid & 31) * 4;      // 0..124

    const float* Abase = A + (size_t)(by * 128) * K;
    const float* Bbase = B + (size_t)bx * 128;

    float acc[8][8];
    #pragma unroll
    for (int i = 0; i < 8; i++)
        #pragma unroll
        for (int j = 0; j < 8; j++) acc[i][j] = 0.f;

    for (int k0 = 0; k0 < K; k0 += 8) {
        float4 av = *(const float4*)(Abase + (size_t)arow * K + k0 + acol);
        As[acol + 0][arow] = av.x;
        As[acol + 1][arow] = av.y;
        As[acol + 2][arow] = av.z;
        As[acol + 3][arow] = av.w;
        float4 bv = *(const float4*)(Bbase + (size_t)(k0 + brow) * N + bcol);
        *(float4*)&Bs[brow][bcol] = bv;
        __syncthreads();
        #pragma unroll
        for (int k = 0; k < 8; k++) {
            float4 a0 = *(const float4*)&As[k][tr * 8];
            float4 a1 = *(const float4*)&As[k][tr * 8 + 4];
            float4 b0 = *(const float4*)&Bs[k][tc * 8];
            float4 b1 = *(const float4*)&Bs[k][tc * 8 + 4];
            float ar[8] = {a0.x, a0.y, a0.z, a0.w, a1.x, a1.y, a1.z, a1.w};
            float br[8] = {b0.x, b0.y, b0.z, b0.w, b1.x, b1.y, b1.z, b1.w};
            #pragma unroll
            for (int i = 0; i < 8; i++)
                #pragma unroll
                for (int j = 0; j < 8; j++)
                    acc[i][j] = fmaf(ar[i], br[j], acc[i][j]);
        }
        __syncthreads();
    }

    // epilogue
    int col0 = bx * 128 + tc * 8;
    float bload[8];
    if (bias) {
        float4 q0 = *(const float4*)(bias + col0);
        float4 q1 = *(const float4*)(bias + col0 + 4);
        bload[0]=q0.x; bload[1]=q0.y; bload[2]=q0.z; bload[3]=q0.w;
        bload[4]=q1.x; bload[5]=q1.y; bload[6]=q1.z; bload[7]=q1.w;
    } else {
        #pragma unroll
        for (int j = 0; j < 8; j++) bload[j] = 0.f;
    }
    size_t cbase = (size_t)(by * 128 + tr * 8) * N + col0;
    #pragma unroll
    for (int i = 0; i < 8; i++) {
        float v[8];
        #pragma unroll
        for (int j = 0; j < 8; j++) v[j] = acc[i][j] + bload[j];
        if (res) {
            float4 e0 = *(const float4*)(res + cbase + (size_t)i * N);
            float4 e1 = *(const float4*)(res + cbase + (size_t)i * N + 4);
            v[0]+=e0.x; v[1]+=e0.y; v[2]+=e0.z; v[3]+=e0.w;
            v[4]+=e1.x; v[5]+=e1.y; v[6]+=e1.z; v[7]+=e1.w;
        }
        if (relu) {
            #pragma unroll
            for (int j = 0; j < 8; j++) v[j] = fmaxf(v[j], 0.f);
        }
        float4 s0 = {v[0], v[1], v[2], v[3]};
        float4 s1 = {v[4], v[5], v[6], v[7]};
        *(float4*)(C + cbase + (size_t)i * N)     = s0;
        *(float4*)(C + cbase + (size_t)i * N + 4) = s1;
    }
}

// ---------------------------------------------------------------------------
// QK^T scores: 64x64 tile per block, only lower-triangular tiles.
// scores[bh, t, s] = 0.125 * sum_d q[b,t,h,d] * k[b,s,h,d]
// ---------------------------------------------------------------------------
__global__ __launch_bounds__(256)
void qk_kernel(const float* __restrict__ qkv, float* __restrict__ scores) {
    int st = blockIdx.x, tt = blockIdx.y;
    if (st > tt) return;
    int bh = blockIdx.z;
    int b = bh >> 4, h = bh & 15;
    const float* Qb = qkv + (size_t)b * TLEN * (3 * CDIM) + h * HDIM;
    const float* Kb = Qb + CDIM;
    float* S = scores + (size_t)bh * TLEN * TLEN;
    __shared__ float Qs[64][64];   // [d][t]
    __shared__ float Ks[64][64];   // [d][s]
    int tid = threadIdx.x;
    int r = tid >> 2;        // 0..63
    int cg = tid & 3;        // 0..3
    int t0 = tt * 64, s0 = st * 64;
    #pragma unroll
    for (int i = 0; i < 4; i++) {
        int c4 = cg + i * 4;         // float4 index 0..15
        float4 qv = *(const float4*)(Qb + (size_t)(t0 + r) * (3 * CDIM) + c4 * 4);
        Qs[c4 * 4 + 0][r] = qv.x; Qs[c4 * 4 + 1][r] = qv.y;
        Qs[c4 * 4 + 2][r] = qv.z; Qs[c4 * 4 + 3][r] = qv.w;
        float4 kv = *(const float4*)(Kb + (size_t)(s0 + r) * (3 * CDIM) + c4 * 4);
        Ks[c4 * 4 + 0][r] = kv.x; Ks[c4 * 4 + 1][r] = kv.y;
        Ks[c4 * 4 + 2][r] = kv.z; Ks[c4 * 4 + 3][r] = kv.w;
    }
    __syncthreads();
    int trow = tid >> 4, tcol = tid & 15;
    float acc[4][4];
    #pragma unroll
    for (int i = 0; i < 4; i++)
        #pragma unroll
        for (int j = 0; j < 4; j++) acc[i][j] = 0.f;
    #pragma unroll 8
    for (int d = 0; d < 64; d++) {
        float4 a = *(const float4*)&Qs[d][trow * 4];
        float4 bb = *(const float4*)&Ks[d][tcol * 4];
        float ar[4] = {a.x, a.y, a.z, a.w};
        float br[4] = {bb.x, bb.y, bb.z, bb.w};
        #pragma unroll
        for (int i = 0; i < 4; i++)
            #pragma unroll
            for (int j = 0; j < 4; j++)
                acc[i][j] = fmaf(ar[i], br[j], acc[i][j]);
    }
    const float scale = 0.125f;
    #pragma unroll
    for (int i = 0; i < 4; i++) {
        float4 s4 = {acc[i][0] * scale, acc[i][1] * scale,
                     acc[i][2] * scale, acc[i][3] * scale};
        *(float4*)(S + (size_t)(t0 + trow * 4 + i) * TLEN + s0 + tcol * 4) = s4;
    }
}

// ---------------------------------------------------------------------------
// Causal softmax in-place. One warp per row; zeros written for s > t.
// ---------------------------------------------------------------------------
__global__ void softmax_kernel(float* __restrict__ scores) {
    int warp = threadIdx.x >> 5, lane = threadIdx.x & 31;
    size_t row = (size_t)blockIdx.x * 4 + warp;     // 0..65535
    int t = (int)(row & (TLEN - 1));
    float* S = scores + row * TLEN;
    float m = -1e30f, l = 0.f;
    for (int s = lane; s <= t; s += 32) {
        float v = S[s];
        float nm = fmaxf(m, v);
        l = l * __expf(m - nm) + __expf(v - nm);
        m = nm;
    }
    #pragma unroll
    for (int o = 16; o > 0; o >>= 1) {
        float m2 = __shfl_xor_sync(0xffffffffu, m, o);
        float l2 = __shfl_xor_sync(0xffffffffu, l, o);
        float nm = fmaxf(m, m2);
        l = l * __expf(m - nm) + l2 * __expf(m2 - nm);
        m = nm;
    }
    float inv = 1.f / l;
    for (int s = lane; s < TLEN; s += 32) {
        float v = (s <= t) ? __expf(S[s] - m) * inv : 0.f;
        S[s] = v;
    }
}

// ---------------------------------------------------------------------------
// AV: o[b,t,h,d] = sum_s p[bh,t,s] * v[b,s,h,d]. 64(t) x 64(d) per block,
// causal K loop (s only up to end of this t-tile).
// ---------------------------------------------------------------------------
__global__ __launch_bounds__(256)
void av_kernel(const float* __restrict__ scores, const float* __restrict__ qkv,
               float* __restrict__ o) {
    int tt = blockIdx.x;
    int bh = blockIdx.y;
    int b = bh >> 4, h = bh & 15;
    const float* P = scores + (size_t)bh * TLEN * TLEN + (size_t)tt * 64 * TLEN;
    const float* V = qkv + (size_t)b * TLEN * (3 * CDIM) + 2 * CDIM + h * HDIM;
    int tid = threadIdx.x;
    __shared__ float Ps[64][64];   // [s][t]
    __shared__ float Vs[64][64];   // [s][d]
    int r = tid >> 2, cg = tid & 3;
    int trow = tid >> 4, tcol = tid & 15;
    float acc[4][4];
    #pragma unroll
    for (int i = 0; i < 4; i++)
        #pragma unroll
        for (int j = 0; j < 4; j++) acc[i][j] = 0.f;
    int nk = (tt + 1) * 64;
    for (int s0 = 0; s0 < nk; s0 += 64) {
        #pragma unroll
        for (int i = 0; i < 4; i++) {
            int c4 = cg + i * 4;
            float4 pv = *(const float4*)(P + (size_t)r * TLEN + s0 + c4 * 4);
            Ps[c4 * 4 + 0][r] = pv.x; Ps[c4 * 4 + 1][r] = pv.y;
            Ps[c4 * 4 + 2][r] = pv.z; Ps[c4 * 4 + 3][r] = pv.w;
            float4 vv = *(const float4*)(V + (size_t)(s0 + r) * (3 * CDIM) + c4 * 4);
            *(float4*)&Vs[r][c4 * 4] = vv;
        }
        __syncthreads();
        #pragma unroll 8
        for (int s = 0; s < 64; s++) {
            float4 a = *(const float4*)&Ps[s][trow * 4];
            float4 bb = *(const float4*)&Vs[s][tcol * 4];
            float ar[4] = {a.x, a.y, a.z, a.w};
            float br[4] = {bb.x, bb.y, bb.z, bb.w};
            #pragma unroll
            for (int i = 0; i < 4; i++)
                #pragma unroll
                for (int j = 0; j < 4; j++)
                    acc[i][j] = fmaf(ar[i], br[j], acc[i][j]);
        }
        __syncthreads();
    }
    int t0 = tt * 64;
    #pragma unroll
    for (int i = 0; i < 4; i++) {
        float4 s4 = {acc[i][0], acc[i][1], acc[i][2], acc[i][3]};
        *(float4*)(o + (size_t)(b * TLEN + t0 + trow * 4 + i) * CDIM
                     + h * HDIM + tcol * 4) = s4;
    }
}

// ---------------------------------------------------------------------------
// Host orchestration
// ---------------------------------------------------------------------------
extern "C" void kernel_launch(void* const* d_in, const int* in_sizes, int n_in,
                              void* d_out, int out_size) {
    const int*   idx   = (const int*)d_in[0];
    const float* tok   = (const float*)d_in[1];
    const float* pos   = (const float*)d_in[2];
    const float* wq    = (const float*)d_in[3];
    const float* wk    = (const float*)d_in[4];
    const float* wv    = (const float*)d_in[5];
    const float* wproj = (const float*)d_in[6];
    const float* bproj = (const float*)d_in[7];
    const float* ln1g  = (const float*)d_in[8];
    const float* ln1b  = (const float*)d_in[9];
    const float* ln2g  = (const float*)d_in[10];
    const float* ln2b  = (const float*)d_in[11];
    const float* w1    = (const float*)d_in[12];
    const float* b1    = (const float*)d_in[13];
    const float* w2    = (const float*)d_in[14];
    const float* b2    = (const float*)d_in[15];
    const float* lnfg  = (const float*)d_in[16];
    const float* lnfb  = (const float*)d_in[17];
    const float* wlm   = (const float*)d_in[18];
    const float* blm   = (const float*)d_in[19];
    float* out = (float*)d_out;

    float *px, *ph, *pqkv, *po, *pff, *pscores, *pwqkv;
    cudaGetSymbolAddress((void**)&px, g_x);
    cudaGetSymbolAddress((void**)&ph, g_h);
    cudaGetSymbolAddress((void**)&pqkv, g_qkv);
    cudaGetSymbolAddress((void**)&po, g_o);
    cudaGetSymbolAddress((void**)&pff, g_ff);
    cudaGetSymbolAddress((void**)&pscores, g_scores);
    cudaGetSymbolAddress((void**)&pwqkv, g_wqkv);

    // pack fused QKV weights
    {
        size_t total = (size_t)NLAYER * NHEAD * CDIM * HDIM;
        pack_qkv_kernel<<<(unsigned)((total + 255) / 256), 256>>>(wq, wk, wv, pwqkv);
    }
    // embeddings
    embed_kernel<<<NTOK, 256>>>(idx, tok, pos, px);

    for (int l = 0; l < NLAYER; l++) {
        // LN1
        ln_kernel<<<NTOK, 256>>>(px, ln1g + (size_t)l * CDIM, ln1b + (size_t)l * CDIM, ph);
        // QKV GEMM: [4096,1024] x [1024,3072]
        {
            dim3 grid(3 * CDIM / 128, NTOK / 128);
            sgemm_kernel<<<grid, 256>>>(ph, pwqkv + (size_t)l * CDIM * 3 * CDIM,
                                        pqkv, NTOK, 3 * CDIM, CDIM,
                                        nullptr, nullptr, 0);
        }
        // scores (lower-triangular tiles only)
        {
            dim3 grid(TLEN / 64, TLEN / 64, BATCH * NHEAD);
            qk_kernel<<<grid, 256>>>(pqkv, pscores);
        }
        // causal softmax (in place)
        softmax_kernel<<<BATCH * NHEAD * TLEN / 4, 128>>>(pscores);
        // AV
        {
            dim3 grid(TLEN / 64, BATCH * NHEAD);
            av_kernel<<<grid, 256>>>(pscores, pqkv, po);
        }
        // proj + bias + residual -> x
        {
            dim3 grid(CDIM / 128, NTOK / 128);
            sgemm_kernel<<<grid, 256>>>(po, wproj + (size_t)l * CDIM * CDIM, px,
                                        NTOK, CDIM, CDIM,
                                        bproj + (size_t)l * CDIM, px, 0);
        }
        // LN2
        ln_kernel<<<NTOK, 256>>>(px, ln2g + (size_t)l * CDIM, ln2b + (size_t)l * CDIM, ph);
        // MLP up + relu
        {
            dim3 grid(FF / 128, NTOK / 128);
            sgemm_kernel<<<grid, 256>>>(ph, w1 + (size_t)l * CDIM * FF, pff,
                                        NTOK, FF, CDIM,
                                        b1 + (size_t)l * FF, nullptr, 1);
        }
        // MLP down + bias + residual -> x
        {
            dim3 grid(CDIM / 128, NTOK / 128);
            sgemm_kernel<<<grid, 256>>>(pff, w2 + (size_t)l * FF * CDIM, px,
                                        NTOK, CDIM, FF,
                                        b2 + (size_t)l * CDIM, px, 0);
        }
    }
    // final LN
    ln_kernel<<<NTOK, 256>>>(px, lnfg, lnfb, ph);
    // LM head: [4096,1024] x [1024,32000]
    {
        dim3 grid(VOCAB / 128, NTOK / 128);
        sgemm_kernel<<<grid, 256>>>(ph, wlm, out, NTOK, VOCAB, CDIM,
                                    blm, nullptr, 0);
    }
}